// round 8
// baseline (speedup 1.0000x reference)
#include <cuda_runtime.h>
#include <cuda_bf16.h>
#include <math.h>
#include <stdint.h>

// Problem constants
#define BB   4
#define NSEQ 4096
#define EE   1024
#define HH   16
#define DD   64
#define MM   256
#define TT   (BB*NSEQ)     // 16384
#define BHn  (BB*HH)       // 64
#define NSEG 8

#define RATIO 0.0625f
#define EPSK  1e-4f
#define SCQ   0.3535533905932738f   // 64^-0.25

// ---------------- device scratch ----------------
__device__ float g_q[(size_t)BHn*NSEQ*DD];
__device__ float g_k[(size_t)BHn*NSEQ*DD];
__device__ float g_v[(size_t)BHn*NSEQ*DD];
__device__ float g_ksum[BHn*MM];
__device__ float g_ksump[(size_t)NSEG*BHn*MM];
__device__ float g_svp[(size_t)NSEG*BHn*DD];
__device__ float g_ctxp[(size_t)NSEG*BHn*MM*DD];
__device__ float g_ctx[BHn*MM*DD];
__device__ float g_kstab;
__device__ __nv_bfloat16 g_ah[(size_t)TT*EE];
__device__ __nv_bfloat16 g_al[(size_t)TT*EE];
__device__ __nv_bfloat16 g_wh[(size_t)EE*EE];
__device__ __nv_bfloat16 g_wl[(size_t)EE*EE];

// ---------------- helpers ----------------
__device__ __forceinline__ void atomicMaxFloat(float* addr, float v) {
    if (v >= 0.f) atomicMax((int*)addr, __float_as_int(v));
    else          atomicMin((unsigned int*)addr, __float_as_uint(v));
}

__global__ void init_kernel() {
    if (blockIdx.x == 0 && threadIdx.x == 0) g_kstab = -INFINITY;
}

__device__ __forceinline__ uint32_t smem_u32(const void* p) {
    uint32_t a;
    asm("{ .reg .u64 t; cvta.to.shared.u64 t, %1; cvt.u32.u64 %0, t; }" : "=r"(a) : "l"(p));
    return a;
}

__device__ __forceinline__ void mma16816(float* c, const uint32_t* a, const uint32_t* b) {
    asm volatile(
        "mma.sync.aligned.m16n8k16.row.col.f32.bf16.bf16.f32 "
        "{%0,%1,%2,%3},{%4,%5,%6,%7},{%8,%9},{%0,%1,%2,%3};"
        : "+f"(c[0]), "+f"(c[1]), "+f"(c[2]), "+f"(c[3])
        : "r"(a[0]), "r"(a[1]), "r"(a[2]), "r"(a[3]), "r"(b[0]), "r"(b[1]));
}

__device__ __forceinline__ void ldmx4(uint32_t* r, uint32_t addr) {
    asm volatile("ldmatrix.sync.aligned.m8n8.x4.shared.b16 {%0,%1,%2,%3}, [%4];"
        : "=r"(r[0]), "=r"(r[1]), "=r"(r[2]), "=r"(r[3]) : "r"(addr));
}

// packed fp32x2
__device__ __forceinline__ void fma2(unsigned long long& d, unsigned long long a, unsigned long long b) {
    asm("fma.rn.f32x2 %0, %1, %2, %0;" : "+l"(d) : "l"(a), "l"(b));
}
__device__ __forceinline__ unsigned long long pack2(float x) {
    unsigned long long r;
    asm("mov.b64 %0, {%1, %1};" : "=l"(r) : "f"(x));
    return r;
}
__device__ __forceinline__ float2 unpack2(unsigned long long v) {
    float2 f;
    asm("mov.b64 {%0, %1}, %2;" : "=f"(f.x), "=f"(f.y) : "l"(v));
    return f;
}
__device__ __forceinline__ float f4c(const float4& v, int j) {
    return j == 0 ? v.x : j == 1 ? v.y : j == 2 ? v.z : v.w;
}

// ---------------- fp32 -> bf16 hi/lo split ----------------
__global__ __launch_bounds__(256) void split_kernel(
    const float* __restrict__ src, __nv_bfloat16* __restrict__ hi,
    __nv_bfloat16* __restrict__ lo, int n4)
{
    const float4* s4 = (const float4*)src;
    uint2* h2 = (uint2*)hi;
    uint2* l2 = (uint2*)lo;
    for (int i = blockIdx.x * 256 + threadIdx.x; i < n4; i += gridDim.x * 256) {
        float4 v = s4[i];
        __nv_bfloat16 h0 = __float2bfloat16(v.x);
        __nv_bfloat16 h1 = __float2bfloat16(v.y);
        __nv_bfloat16 h2b = __float2bfloat16(v.z);
        __nv_bfloat16 h3 = __float2bfloat16(v.w);
        __nv_bfloat16 l0 = __float2bfloat16(v.x - __bfloat162float(h0));
        __nv_bfloat16 l1 = __float2bfloat16(v.y - __bfloat162float(h1));
        __nv_bfloat16 l2b = __float2bfloat16(v.z - __bfloat162float(h2b));
        __nv_bfloat16 l3 = __float2bfloat16(v.w - __bfloat162float(h3));
        uint2 hv, lv;
        hv.x = ((uint32_t)__bfloat16_as_ushort(h1) << 16) | __bfloat16_as_ushort(h0);
        hv.y = ((uint32_t)__bfloat16_as_ushort(h3) << 16) | __bfloat16_as_ushort(h2b);
        lv.x = ((uint32_t)__bfloat16_as_ushort(l1) << 16) | __bfloat16_as_ushort(l0);
        lv.y = ((uint32_t)__bfloat16_as_ushort(l3) << 16) | __bfloat16_as_ushort(l2b);
        h2[i] = hv;
        l2[i] = lv;
    }
}

// ---------------- bf16-split mma.sync GEMM: K-chunk 64, 3-stage, ldmatrix (R7 known-good) ----------------
#define NCHUNK 48          // 3 passes * 1024/64
#define STG_BYTES 32768    // A(16K) + B(16K) per stage

template<int OUT_MODE>
__global__ __launch_bounds__(256) void gemm_mma(
    const __nv_bfloat16* __restrict__ Ah, const __nv_bfloat16* __restrict__ Al,
    const __nv_bfloat16* __restrict__ Wh, const __nv_bfloat16* __restrict__ Wl,
    const float* __restrict__ bias, float* __restrict__ C)
{
    extern __shared__ __align__(128) char gsm[];

    const int tid  = threadIdx.x;
    const int lane = tid & 31;
    const int wid  = tid >> 5;
    const int wm   = wid & 1;
    const int wn   = wid >> 1;
    const int bm   = blockIdx.y * 128;
    const int bn   = blockIdx.x * 128;

    const __nv_bfloat16* pA[3] = {Ah, Ah, Al};
    const __nv_bfloat16* pB[3] = {Wh, Wl, Wh};

    float c[4][4][4];
#pragma unroll
    for (int i = 0; i < 4; i++)
#pragma unroll
        for (int j = 0; j < 4; j++)
#pragma unroll
            for (int q = 0; q < 4; q++) c[i][j][q] = 0.f;

    const uint32_t smem_base = smem_u32(gsm);

    auto prefetch = [&](int s, int stage) {
        if (s < NCHUNK) {
            const int ph = s >> 4;
            const int kk = (s & 15) << 6;
            const __nv_bfloat16* gA = pA[ph];
            const __nv_bfloat16* gB = pB[ph];
            const uint32_t aB = smem_base + stage * STG_BYTES;
            const uint32_t bB = aB + 16384;
#pragma unroll
            for (int it = 0; it < 4; it++) {
                int idx = it * 256 + tid;
                int row = idx >> 3;
                int pb  = idx & 7;
                uint32_t doff = row * 128 + ((pb ^ (row & 7)) << 4);
                const void* srcA = gA + (size_t)(bm + row) * EE + kk + pb * 8;
                const void* srcB = gB + (size_t)(bn + row) * EE + kk + pb * 8;
                asm volatile("cp.async.cg.shared.global [%0], [%1], 16;" :: "r"(aB + doff), "l"(srcA));
                asm volatile("cp.async.cg.shared.global [%0], [%1], 16;" :: "r"(bB + doff), "l"(srcB));
            }
        }
        asm volatile("cp.async.commit_group;" ::: "memory");
    };

    prefetch(0, 0);
    prefetch(1, 1);

    for (int s = 0; s < NCHUNK; s++) {
        const int stage = s % 3;
        asm volatile("cp.async.wait_group 1;" ::: "memory");
        __syncthreads();
        prefetch(s + 2, (s + 2) % 3);

        const uint32_t cA = smem_base + stage * STG_BYTES;
        const uint32_t cB = cA + 16384;
#pragma unroll
        for (int ks = 0; ks < 4; ks++) {
            uint32_t bf[4][2];
#pragma unroll
            for (int jb = 0; jb < 2; jb++) {
                int row = wn * 32 + jb * 16 + ((lane >> 4) << 3) + (lane & 7);
                int pb  = ks * 2 + ((lane >> 3) & 1);
                uint32_t ad = cB + row * 128 + ((pb ^ (row & 7)) << 4);
                uint32_t t4[4];
                ldmx4(t4, ad);
                bf[jb * 2][0] = t4[0]; bf[jb * 2][1] = t4[1];
                bf[jb * 2 + 1][0] = t4[2]; bf[jb * 2 + 1][1] = t4[3];
            }
#pragma unroll
            for (int i = 0; i < 4; i++) {
                int r0 = wm * 64 + i * 16;
                int row = r0 + (((lane >> 3) & 1) << 3) + (lane & 7);
                int pb  = ks * 2 + ((lane >> 4) & 1);
                uint32_t ad = cA + row * 128 + ((pb ^ (row & 7)) << 4);
                uint32_t af[4];
                ldmx4(af, ad);
#pragma unroll
                for (int j = 0; j < 4; j++)
                    mma16816(c[i][j], af, bf[j]);
            }
        }
        __syncthreads();
    }

#pragma unroll
    for (int i = 0; i < 4; i++) {
        int r = bm + wm * 64 + i * 16 + (lane >> 2);
#pragma unroll
        for (int j = 0; j < 4; j++) {
            int col = bn + wn * 32 + j * 8 + (lane & 3) * 2;
            float b0 = bias[col], b1 = bias[col + 1];
            float2 v0 = make_float2(c[i][j][0] + b0, c[i][j][1] + b1);
            float2 v1 = make_float2(c[i][j][2] + b0, c[i][j][3] + b1);
            if (OUT_MODE == 0) {
                *(float2*)(C + (size_t)r * EE + col)       = v0;
                *(float2*)(C + (size_t)(r + 8) * EE + col) = v1;
            } else {
                int h_ = col >> 6, d0 = col & 63;
                int b_ = r >> 12, n_ = r & 4095;
                size_t base = ((size_t)(b_ * HH + h_) * NSEQ);
                *(float2*)(C + (base + n_)     * DD + d0) = v0;
                *(float2*)(C + (base + n_ + 8) * DD + d0) = v1;
            }
        }
    }
}

// ---------------- fused: unstabilized k-features + context/ksum/sv partials + global dd max ----------------
__global__ __launch_bounds__(256, 2) void ctx_fused(
    const float* __restrict__ K, const float* __restrict__ V,
    const float* __restrict__ proj)
{
    extern __shared__ float sm[];
    float* sPT = sm;               // [64][256]   64 KB
    float* sKF = sPT + DD * MM;    // [32][256]   32 KB
    float* sXk = sKF + 32 * MM;    // [32][64]     8 KB
    float* sV  = sXk + 32 * DD;    // [32][64]     8 KB
    __shared__ float swm[8];

    const int tid = threadIdx.x;
    const int bh  = blockIdx.x;
    const int seg = blockIdx.y;
    const int lane = tid & 31;
    const int w    = tid >> 5;
    const int m0   = lane * 8;
    const int tx   = tid & 15;     // d group (4 d)
    const int ty   = tid >> 4;     // m group (16 m)

    {
        const float4* pr = (const float4*)(proj + tid * DD);
#pragma unroll
        for (int t = 0; t < 16; t++) {
            float4 v = pr[t];
            int d = t * 4;
            sPT[(d + 0) * MM + tid] = v.x;
            sPT[(d + 1) * MM + tid] = v.y;
            sPT[(d + 2) * MM + tid] = v.z;
            sPT[(d + 3) * MM + tid] = v.w;
        }
    }

    unsigned long long cacc[16][2];
#pragma unroll
    for (int i = 0; i < 16; i++) { cacc[i][0] = 0ull; cacc[i][1] = 0ull; }
    float kacc = 0.f;
    float svacc = 0.f;
    float ddmax = -1e30f;

    for (int it = 0; it < 16; it++) {
        const int n0 = seg * 512 + it * 32;
        __syncthreads();
        {
            const float4* kr = (const float4*)(K + ((size_t)bh * NSEQ + n0) * DD);
            const float4* vr = (const float4*)(V + ((size_t)bh * NSEQ + n0) * DD);
            float4* sk4 = (float4*)sXk;
            float4* sv4 = (float4*)sV;
#pragma unroll
            for (int i = 0; i < 2; i++) {
                int f = tid * 2 + i;
                float4 kv = kr[f];
                sk4[f] = make_float4(kv.x * SCQ, kv.y * SCQ, kv.z * SCQ, kv.w * SCQ);
                sv4[f] = vr[f];
            }
        }
        __syncthreads();

        // dd + unstabilized exp -> sKF (4 rows per warp), register-blocked over d
        {
            unsigned long long a2[4][4];
#pragma unroll
            for (int r = 0; r < 4; r++)
#pragma unroll
                for (int j = 0; j < 4; j++) a2[r][j] = 0ull;

#pragma unroll 2
            for (int d0 = 0; d0 < DD; d0 += 4) {
                float4 xv[4];
#pragma unroll
                for (int r = 0; r < 4; r++)
                    xv[r] = *(const float4*)&sXk[(w * 4 + r) * DD + d0];
#pragma unroll
                for (int dd = 0; dd < 4; dd++) {
                    const ulonglong2* bp = (const ulonglong2*)&sPT[(d0 + dd) * MM + m0];
                    ulonglong2 b01 = bp[0], b23 = bp[1];
#pragma unroll
                    for (int r = 0; r < 4; r++) {
                        unsigned long long av = pack2(f4c(xv[r], dd));
                        fma2(a2[r][0], av, b01.x); fma2(a2[r][1], av, b01.y);
                        fma2(a2[r][2], av, b23.x); fma2(a2[r][3], av, b23.y);
                    }
                }
            }
#pragma unroll
            for (int r = 0; r < 4; r++) {
                const float* xr = &sXk[(w * 4 + r) * DD];
                float x0 = xr[lane * 2], x1 = xr[lane * 2 + 1];
                float p = x0 * x0 + x1 * x1;
#pragma unroll
                for (int o = 16; o > 0; o >>= 1) p += __shfl_xor_sync(0xffffffffu, p, o);
                float sub = 0.5f * p;
                float o8[8];
#pragma unroll
                for (int j = 0; j < 4; j++) {
                    float2 f = unpack2(a2[r][j]);
                    ddmax = fmaxf(ddmax, fmaxf(f.x, f.y));
                    o8[j * 2]     = __expf(f.x - sub);
                    o8[j * 2 + 1] = __expf(f.y - sub);
                }
                float4* dst = (float4*)&sKF[(w * 4 + r) * MM + m0];
                dst[0] = *(float4*)(o8);
                dst[1] = *(float4*)(o8 + 4);
            }
        }
        __syncthreads();

#pragma unroll
        for (int r = 0; r < 32; r++) kacc += sKF[r * MM + tid];

        if (tid < 64) {
#pragma unroll
            for (int r = 0; r < 32; r++) svacc += sV[r * DD + tid];
        }

        // U partial, register-blocked kf reads (4x LDS.128 per row)
        const ulonglong2* sV2 = (const ulonglong2*)sV;
#pragma unroll 2
        for (int r = 0; r < 32; r++) {
            ulonglong2 bv = sV2[r * 16 + tx];
            const float4* kf4 = (const float4*)&sKF[r * MM + ty * 16];
            float4 kq[4];
            kq[0] = kf4[0]; kq[1] = kf4[1]; kq[2] = kf4[2]; kq[3] = kf4[3];
#pragma unroll
            for (int q = 0; q < 4; q++) {
#pragma unroll
                for (int j = 0; j < 4; j++) {
                    unsigned long long av = pack2(f4c(kq[q], j));
                    fma2(cacc[q * 4 + j][0], av, bv.x);
                    fma2(cacc[q * 4 + j][1], av, bv.y);
                }
            }
        }
    }

    g_ksump[((size_t)seg * BHn + bh) * MM + tid] = kacc;
    if (tid < 64) g_svp[((size_t)seg * BHn + bh) * DD + tid] = svacc;

    float* cp = g_ctxp + ((size_t)seg * BHn + bh) * MM * DD;
#pragma unroll
    for (int i = 0; i < 16; i++) {
        float2 f0 = unpack2(cacc[i][0]);
        float2 f1 = unpack2(cacc[i][1]);
        *(float4*)(cp + (ty * 16 + i) * DD + tx * 4) = make_float4(f0.x, f0.y, f1.x, f1.y);
    }

#pragma unroll
    for (int o = 16; o > 0; o >>= 1)
        ddmax = fmaxf(ddmax, __shfl_xor_sync(0xffffffffu, ddmax, o));
    if (lane == 0) swm[w] = ddmax;
    __syncthreads();
    if (tid == 0) {
        float m = swm[0];
#pragma unroll
        for (int i = 1; i < 8; i++) m = fmaxf(m, swm[i]);
        atomicMaxFloat(&g_kstab, m);
    }
}

// ---------------- assemble ctx + ksum from unstabilized partials ----------------
__global__ __launch_bounds__(256) void ctx_reduce_kernel() {
    const float escale = __expf(-g_kstab);
    int i = blockIdx.x * 256 + threadIdx.x;
    if (i < BHn * MM * DD) {
        int bh = i >> 14;
        int d  = i & 63;
        float U = 0.f, Sv = 0.f;
#pragma unroll
        for (int seg = 0; seg < NSEG; seg++) {
            U  += g_ctxp[(size_t)seg * BHn * MM * DD + i];
            Sv += g_svp[((size_t)seg * BHn + bh) * DD + d];
        }
        g_ctx[i] = RATIO * (escale * U + EPSK * Sv);
    }
    if (i < BHn * MM) {
        float T = 0.f;
#pragma unroll
        for (int seg = 0; seg < NSEG; seg++)
            T += g_ksump[(size_t)seg * BHn * MM + i];
        g_ksum[i] = RATIO * (escale * T + EPSK * (float)NSEQ);
    }
}

// ---------------- fused query features + attention combine + bf16 split output ----------------
__global__ __launch_bounds__(256) void attn_fused(
    const float* __restrict__ Q, const float* __restrict__ proj,
    __nv_bfloat16* __restrict__ OutH, __nv_bfloat16* __restrict__ OutL)
{
    extern __shared__ float sm[];
    float* sPT  = sm;                 // [64][256]  64 KB
    float* sCtx = sPT + DD * MM;      // [256][64]  64 KB
    float* sQF  = sCtx + MM * DD;     // [32][256]  32 KB
    float* sX   = sQF + 32 * MM;      // [32][64]    8 KB
    float* sKs  = sX + 32 * DD;       // [256]
    float* sDp  = sKs + MM;           // [32]

    const int tid = threadIdx.x;
    const int bh  = blockIdx.x;
    const int b   = bh >> 4;
    const int h   = bh & 15;
    const int nblk = blockIdx.y * 512;
    const int lane = tid & 31;
    const int w    = tid >> 5;
    const int m0   = lane * 8;
    const int hl   = lane >> 4;
    const int dl   = lane & 15;

    {
        const float4* pr = (const float4*)(proj + tid * DD);
#pragma unroll
        for (int t = 0; t < 16; t++) {
            float4 v = pr[t];
            int d = t * 4;
            sPT[(d + 0) * MM + tid] = v.x;
            sPT[(d + 1) * MM + tid] = v.y;
            sPT[(d + 2) * MM + tid] = v.z;
            sPT[(d + 3) * MM + tid] = v.w;
        }
        const float4* cb = (const float4*)(g_ctx + (size_t)bh * MM * DD);
        float4* sc4 = (float4*)sCtx;
#pragma unroll
        for (int t = 0; t < 16; t++) sc4[tid + t * 256] = cb[tid + t * 256];
        sKs[tid] = g_ksum[bh * MM + tid];
    }

    for (int it = 0; it < 16; it++) {
        const int n0 = nblk + it * 32;
        __syncthreads();
        {
            const float4* xr = (const float4*)(Q + ((size_t)bh * NSEQ + n0) * DD);
            float4* sx4 = (float4*)sX;
#pragma unroll
            for (int i = 0; i < 2; i++) {
                int f = tid * 2 + i;
                float4 v = xr[f];
                sx4[f] = make_float4(v.x * SCQ, v.y * SCQ, v.z * SCQ, v.w * SCQ);
            }
        }
        __syncthreads();

        // qf: dd + per-row max + exp + dp (4 rows per warp), register-blocked over d
        {
            unsigned long long a2[4][4];
#pragma unroll
            for (int r = 0; r < 4; r++)
#pragma unroll
                for (int j = 0; j < 4; j++) a2[r][j] = 0ull;

#pragma unroll 2
            for (int d0 = 0; d0 < DD; d0 += 4) {
                float4 xv[4];
#pragma unroll
                for (int r = 0; r < 4; r++)
                    xv[r] = *(const float4*)&sX[(w * 4 + r) * DD + d0];
#pragma unroll
                for (int dd = 0; dd < 4; dd++) {
                    const ulonglong2* bp = (const ulonglong2*)&sPT[(d0 + dd) * MM + m0];
                    ulonglong2 b01 = bp[0], b23 = bp[1];
#pragma unroll
                    for (int r = 0; r < 4; r++) {
                        unsigned long long av = pack2(f4c(xv[r], dd));
                        fma2(a2[r][0], av, b01.x); fma2(a2[r][1], av, b01.y);
                        fma2(a2[r][2], av, b23.x); fma2(a2[r][3], av, b23.y);
                    }
                }
            }
#pragma unroll
            for (int r = 0; r < 4; r++) {
                float v8[8];
#pragma unroll
                for (int j = 0; j < 4; j++) {
                    float2 f = unpack2(a2[r][j]);
                    v8[j * 2] = f.x; v8[j * 2 + 1] = f.y;
                }
                float mx = v8[0];
#pragma unroll
                for (int j = 1; j < 8; j++) mx = fmaxf(mx, v8[j]);
#pragma unroll
                for (int o = 16; o > 0; o >>= 1)
                    mx = fmaxf(mx, __shfl_xor_sync(0xffffffffu, mx, o));

                const float* xr = &sX[(w * 4 + r) * DD];
                float x0 = xr[lane * 2], x1 = xr[lane * 2 + 1];
                float p = x0 * x0 + x1 * x1;
#pragma unroll
                for (int o = 16; o > 0; o >>= 1) p += __shfl_xor_sync(0xffffffffu, p, o);
                float sub = 0.5f * p + mx;

                float o8[8];
                float dp = 0.f;
#pragma unroll
                for (int j = 0; j < 8; j++) {
                    o8[j] = RATIO * (__expf(v8[j] - sub) + EPSK);
                    dp += o8[j] * sKs[m0 + j];
                }
#pragma unroll
                for (int o = 16; o > 0; o >>= 1) dp += __shfl_xor_sync(0xffffffffu, dp, o);
                if (lane == 0) sDp[w * 4 + r] = dp;

                float4* dst = (float4*)&sQF[(w * 4 + r) * MM + m0];
                dst[0] = *(float4*)(o8);
                dst[1] = *(float4*)(o8 + 4);
            }
        }
        __syncwarp();

        // combine + bf16 hi/lo split output, register-blocked q reads
        {
            const int rowA = w * 4 + hl;
            const int rowB = w * 4 + 2 + hl;
            const float* qA = &sQF[rowA * MM];
            const float* qB = &sQF[rowB * MM];
            unsigned long long aA0 = 0ull, aA1 = 0ull, aB0 = 0ull, aB1 = 0ull;
#pragma unroll 4
            for (int mb = 0; mb < MM; mb += 4) {
                float4 qa4 = *(const float4*)&qA[mb];
                float4 qb4 = *(const float4*)&qB[mb];
#pragma unroll
                for (int j = 0; j < 4; j++) {
                    ulonglong2 cv = *(const ulonglong2*)&sCtx[(mb + j) * DD + dl * 4];
                    unsigned long long qa = pack2(f4c(qa4, j));
                    unsigned long long qb = pack2(f4c(qb4, j));
                    fma2(aA0, qa, cv.x); fma2(aA1, qa, cv.y);
                    fma2(aB0, qb, cv.x); fma2(aB1, qb, cv.y);
                }
            }
            float dA = 1.f / sDp[rowA];
            float dB = 1.f / sDp[rowB];
            float2 fA0 = unpack2(aA0), fA1 = unpack2(aA1);
            float2 fB0 = unpack2(aB0), fB1 = unpack2(aB1);
            float oA[4] = {fA0.x * dA, fA0.y * dA, fA1.x * dA, fA1.y * dA};
            float oB[4] = {fB0.x * dB, fB0.y * dB, fB1.x * dB, fB1.y * dB};

            size_t idxA = ((size_t)(b * NSEQ + n0 + rowA)) * EE + h * DD + dl * 4;
            size_t idxB = ((size_t)(b * NSEQ + n0 + rowB)) * EE + h * DD + dl * 4;

            ushort hA[4], lA[4], hB[4], lB[4];
#pragma unroll
            for (int j = 0; j < 4; j++) {
                __nv_bfloat16 hb = __float2bfloat16(oA[j]);
                hA[j] = __bfloat16_as_ushort(hb);
                lA[j] = __bfloat16_as_ushort(__float2bfloat16(oA[j] - __bfloat162float(hb)));
                __nv_bfloat16 hb2 = __float2bfloat16(oB[j]);
                hB[j] = __bfloat16_as_ushort(hb2);
                lB[j] = __bfloat16_as_ushort(__float2bfloat16(oB[j] - __bfloat162float(hb2)));
            }
            uint2 hvA, lvA, hvB, lvB;
            hvA.x = ((uint32_t)hA[1] << 16) | hA[0]; hvA.y = ((uint32_t)hA[3] << 16) | hA[2];
            lvA.x = ((uint32_t)lA[1] << 16) | lA[0]; lvA.y = ((uint32_t)lA[3] << 16) | lA[2];
            hvB.x = ((uint32_t)hB[1] << 16) | hB[0]; hvB.y = ((uint32_t)hB[3] << 16) | hB[2];
            lvB.x = ((uint32_t)lB[1] << 16) | lB[0]; lvB.y = ((uint32_t)lB[3] << 16) | lB[2];
            *(uint2*)(OutH + idxA) = hvA;
            *(uint2*)(OutL + idxA) = lvA;
            *(uint2*)(OutH + idxB) = hvB;
            *(uint2*)(OutL + idxB) = lvB;
        }
    }
}

// ---------------- launch ----------------
extern "C" void kernel_launch(void* const* d_in, const int* in_sizes, int n_in,
                              void* d_out, int out_size) {
    const float* x    = (const float*)d_in[0];
    const float* Wq   = (const float*)d_in[1];
    const float* bq   = (const float*)d_in[2];
    const float* Wk   = (const float*)d_in[3];
    const float* bk   = (const float*)d_in[4];
    const float* Wv   = (const float*)d_in[5];
    const float* bv   = (const float*)d_in[6];
    const float* Wo   = (const float*)d_in[7];
    const float* bo   = (const float*)d_in[8];
    const float* proj = (const float*)d_in[9];
    float* out = (float*)d_out;

    float *pq, *pk, *pv;
    __nv_bfloat16 *pah, *pal, *pwh, *pwl;
    cudaGetSymbolAddress((void**)&pq,  g_q);
    cudaGetSymbolAddress((void**)&pk,  g_k);
    cudaGetSymbolAddress((void**)&pv,  g_v);
    cudaGetSymbolAddress((void**)&pah, g_ah);
    cudaGetSymbolAddress((void**)&pal, g_al);
    cudaGetSymbolAddress((void**)&pwh, g_wh);
    cudaGetSymbolAddress((void**)&pwl, g_wl);

    const int GEMM_SMEM = 3 * STG_BYTES;                                                 // 98304
    const int CTXF_SMEM = (DD * MM + 32 * MM + 32 * DD + 32 * DD) * (int)sizeof(float);  // 114688
    const int ATTN_SMEM = (DD * MM + MM * DD + 32 * MM + 32 * DD + MM + 32) * (int)sizeof(float); // 173184
    cudaFuncSetAttribute(gemm_mma<0>, cudaFuncAttributeMaxDynamicSharedMemorySize, GEMM_SMEM);
    cudaFuncSetAttribute(gemm_mma<1>, cudaFuncAttributeMaxDynamicSharedMemorySize, GEMM_SMEM);
    cudaFuncSetAttribute(ctx_fused,  cudaFuncAttributeMaxDynamicSharedMemorySize, CTXF_SMEM);
    cudaFuncSetAttribute(attn_fused, cudaFuncAttributeMaxDynamicSharedMemorySize, ATTN_SMEM);

    init_kernel<<<1, 32>>>();

    split_kernel<<<2048, 256>>>(x, pah, pal, TT * EE / 4);

    dim3 gg(EE / 128, TT / 128);

    split_kernel<<<512, 256>>>(Wq, pwh, pwl, EE * EE / 4);
    gemm_mma<1><<<gg, 256, GEMM_SMEM>>>(pah, pal, pwh, pwl, bq, pq);
    split_kernel<<<512, 256>>>(Wk, pwh, pwl, EE * EE / 4);
    gemm_mma<1><<<gg, 256, GEMM_SMEM>>>(pah, pal, pwh, pwl, bk, pk);
    split_kernel<<<512, 256>>>(Wv, pwh, pwl, EE * EE / 4);
    gemm_mma<1><<<gg, 256, GEMM_SMEM>>>(pah, pal, pwh, pwl, bv, pv);

    ctx_fused<<<dim3(BHn, NSEG), 256, CTXF_SMEM>>>(pk, pv, proj);
    ctx_reduce_kernel<<<(BHn * MM * DD + 255) / 256, 256>>>();

    attn_fused<<<dim3(BHn, 8), 256, ATTN_SMEM>>>(pq, proj, pah, pal);

    split_kernel<<<512, 256>>>(Wo, pwh, pwl, EE * EE / 4);
    gemm_mma<0><<<gg, 256, GEMM_SMEM>>>(pah, pal, pwh, pwl, bo, out);
}

// round 9
// speedup vs baseline: 1.1490x; 1.1490x over previous
#include <cuda_runtime.h>
#include <cuda_bf16.h>
#include <math.h>
#include <stdint.h>

// Problem constants
#define BB   4
#define NSEQ 4096
#define EE   1024
#define HH   16
#define DD   64
#define MM   256
#define TT   (BB*NSEQ)     // 16384
#define BHn  (BB*HH)       // 64
#define NSEG 8

#define RATIO 0.0625f
#define EPSK  1e-4f
#define SCQ   0.3535533905932738f   // 64^-0.25

// ---------------- device scratch ----------------
__device__ float g_q[(size_t)BHn*NSEQ*DD];
__device__ float g_k[(size_t)BHn*NSEQ*DD];
__device__ float g_v[(size_t)BHn*NSEQ*DD];
__device__ float g_ksum[BHn*MM];
__device__ float g_ksump[(size_t)NSEG*BHn*MM];
__device__ float g_svp[(size_t)NSEG*BHn*DD];
__device__ float g_ctxp[(size_t)NSEG*BHn*MM*DD];
__device__ float g_ctx[BHn*MM*DD];
__device__ float g_dinv[(size_t)BHn*NSEQ];
__device__ float g_kstab;
__device__ __nv_bfloat16 g_ah[(size_t)TT*EE];
__device__ __nv_bfloat16 g_al[(size_t)TT*EE];
__device__ __nv_bfloat16 g_wh[(size_t)EE*EE];
__device__ __nv_bfloat16 g_wl[(size_t)EE*EE];
__device__ __nv_bfloat16 g_qfh[(size_t)BHn*NSEQ*MM];
__device__ __nv_bfloat16 g_qfl[(size_t)BHn*NSEQ*MM];

// ---------------- helpers ----------------
__device__ __forceinline__ void atomicMaxFloat(float* addr, float v) {
    if (v >= 0.f) atomicMax((int*)addr, __float_as_int(v));
    else          atomicMin((unsigned int*)addr, __float_as_uint(v));
}

__global__ void init_kernel() {
    if (blockIdx.x == 0 && threadIdx.x == 0) g_kstab = -INFINITY;
}

__device__ __forceinline__ uint32_t smem_u32(const void* p) {
    uint32_t a;
    asm("{ .reg .u64 t; cvta.to.shared.u64 t, %1; cvt.u32.u64 %0, t; }" : "=r"(a) : "l"(p));
    return a;
}

__device__ __forceinline__ void mma16816(float* c, const uint32_t* a, const uint32_t* b) {
    asm volatile(
        "mma.sync.aligned.m16n8k16.row.col.f32.bf16.bf16.f32 "
        "{%0,%1,%2,%3},{%4,%5,%6,%7},{%8,%9},{%0,%1,%2,%3};"
        : "+f"(c[0]), "+f"(c[1]), "+f"(c[2]), "+f"(c[3])
        : "r"(a[0]), "r"(a[1]), "r"(a[2]), "r"(a[3]), "r"(b[0]), "r"(b[1]));
}

__device__ __forceinline__ void ldmx4(uint32_t* r, uint32_t addr) {
    asm volatile("ldmatrix.sync.aligned.m8n8.x4.shared.b16 {%0,%1,%2,%3}, [%4];"
        : "=r"(r[0]), "=r"(r[1]), "=r"(r[2]), "=r"(r[3]) : "r"(addr));
}

// packed fp32x2
__device__ __forceinline__ void fma2(unsigned long long& d, unsigned long long a, unsigned long long b) {
    asm("fma.rn.f32x2 %0, %1, %2, %0;" : "+l"(d) : "l"(a), "l"(b));
}
__device__ __forceinline__ unsigned long long pack2(float x) {
    unsigned long long r;
    asm("mov.b64 %0, {%1, %1};" : "=l"(r) : "f"(x));
    return r;
}
__device__ __forceinline__ float2 unpack2(unsigned long long v) {
    float2 f;
    asm("mov.b64 {%0, %1}, %2;" : "=f"(f.x), "=f"(f.y) : "l"(v));
    return f;
}
__device__ __forceinline__ float f4c(const float4& v, int j) {
    return j == 0 ? v.x : j == 1 ? v.y : j == 2 ? v.z : v.w;
}

// ---------------- fp32 -> bf16 hi/lo split ----------------
__global__ __launch_bounds__(256) void split_kernel(
    const float* __restrict__ src, __nv_bfloat16* __restrict__ hi,
    __nv_bfloat16* __restrict__ lo, int n4)
{
    const float4* s4 = (const float4*)src;
    uint2* h2 = (uint2*)hi;
    uint2* l2 = (uint2*)lo;
    for (int i = blockIdx.x * 256 + threadIdx.x; i < n4; i += gridDim.x * 256) {
        float4 v = s4[i];
        __nv_bfloat16 h0 = __float2bfloat16(v.x);
        __nv_bfloat16 h1 = __float2bfloat16(v.y);
        __nv_bfloat16 h2b = __float2bfloat16(v.z);
        __nv_bfloat16 h3 = __float2bfloat16(v.w);
        __nv_bfloat16 l0 = __float2bfloat16(v.x - __bfloat162float(h0));
        __nv_bfloat16 l1 = __float2bfloat16(v.y - __bfloat162float(h1));
        __nv_bfloat16 l2b = __float2bfloat16(v.z - __bfloat162float(h2b));
        __nv_bfloat16 l3 = __float2bfloat16(v.w - __bfloat162float(h3));
        uint2 hv, lv;
        hv.x = ((uint32_t)__bfloat16_as_ushort(h1) << 16) | __bfloat16_as_ushort(h0);
        hv.y = ((uint32_t)__bfloat16_as_ushort(h3) << 16) | __bfloat16_as_ushort(h2b);
        lv.x = ((uint32_t)__bfloat16_as_ushort(l1) << 16) | __bfloat16_as_ushort(l0);
        lv.y = ((uint32_t)__bfloat16_as_ushort(l3) << 16) | __bfloat16_as_ushort(l2b);
        h2[i] = hv;
        l2[i] = lv;
    }
}

// ---------------- bf16-split mma.sync GEMM: K-chunk 64, 3-stage, ldmatrix (R7 known-good) ----------------
#define NCHUNK 48          // 3 passes * 1024/64
#define STG_BYTES 32768    // A(16K) + B(16K) per stage

template<int OUT_MODE>
__global__ __launch_bounds__(256) void gemm_mma(
    const __nv_bfloat16* __restrict__ Ah, const __nv_bfloat16* __restrict__ Al,
    const __nv_bfloat16* __restrict__ Wh, const __nv_bfloat16* __restrict__ Wl,
    const float* __restrict__ bias, float* __restrict__ C)
{
    extern __shared__ __align__(128) char gsm[];

    const int tid  = threadIdx.x;
    const int lane = tid & 31;
    const int wid  = tid >> 5;
    const int wm   = wid & 1;
    const int wn   = wid >> 1;
    const int bm   = blockIdx.y * 128;
    const int bn   = blockIdx.x * 128;

    const __nv_bfloat16* pA[3] = {Ah, Ah, Al};
    const __nv_bfloat16* pB[3] = {Wh, Wl, Wh};

    float c[4][4][4];
#pragma unroll
    for (int i = 0; i < 4; i++)
#pragma unroll
        for (int j = 0; j < 4; j++)
#pragma unroll
            for (int q = 0; q < 4; q++) c[i][j][q] = 0.f;

    const uint32_t smem_base = smem_u32(gsm);

    auto prefetch = [&](int s, int stage) {
        if (s < NCHUNK) {
            const int ph = s >> 4;
            const int kk = (s & 15) << 6;
            const __nv_bfloat16* gA = pA[ph];
            const __nv_bfloat16* gB = pB[ph];
            const uint32_t aB = smem_base + stage * STG_BYTES;
            const uint32_t bB = aB + 16384;
#pragma unroll
            for (int it = 0; it < 4; it++) {
                int idx = it * 256 + tid;
                int row = idx >> 3;
                int pb  = idx & 7;
                uint32_t doff = row * 128 + ((pb ^ (row & 7)) << 4);
                const void* srcA = gA + (size_t)(bm + row) * EE + kk + pb * 8;
                const void* srcB = gB + (size_t)(bn + row) * EE + kk + pb * 8;
                asm volatile("cp.async.cg.shared.global [%0], [%1], 16;" :: "r"(aB + doff), "l"(srcA));
                asm volatile("cp.async.cg.shared.global [%0], [%1], 16;" :: "r"(bB + doff), "l"(srcB));
            }
        }
        asm volatile("cp.async.commit_group;" ::: "memory");
    };

    prefetch(0, 0);
    prefetch(1, 1);

    for (int s = 0; s < NCHUNK; s++) {
        const int stage = s % 3;
        asm volatile("cp.async.wait_group 1;" ::: "memory");
        __syncthreads();
        prefetch(s + 2, (s + 2) % 3);

        const uint32_t cA = smem_base + stage * STG_BYTES;
        const uint32_t cB = cA + 16384;
#pragma unroll
        for (int ks = 0; ks < 4; ks++) {
            uint32_t bf[4][2];
#pragma unroll
            for (int jb = 0; jb < 2; jb++) {
                int row = wn * 32 + jb * 16 + ((lane >> 4) << 3) + (lane & 7);
                int pb  = ks * 2 + ((lane >> 3) & 1);
                uint32_t ad = cB + row * 128 + ((pb ^ (row & 7)) << 4);
                uint32_t t4[4];
                ldmx4(t4, ad);
                bf[jb * 2][0] = t4[0]; bf[jb * 2][1] = t4[1];
                bf[jb * 2 + 1][0] = t4[2]; bf[jb * 2 + 1][1] = t4[3];
            }
#pragma unroll
            for (int i = 0; i < 4; i++) {
                int r0 = wm * 64 + i * 16;
                int row = r0 + (((lane >> 3) & 1) << 3) + (lane & 7);
                int pb  = ks * 2 + ((lane >> 4) & 1);
                uint32_t ad = cA + row * 128 + ((pb ^ (row & 7)) << 4);
                uint32_t af[4];
                ldmx4(af, ad);
#pragma unroll
                for (int j = 0; j < 4; j++)
                    mma16816(c[i][j], af, bf[j]);
            }
        }
        __syncthreads();
    }

#pragma unroll
    for (int i = 0; i < 4; i++) {
        int r = bm + wm * 64 + i * 16 + (lane >> 2);
#pragma unroll
        for (int j = 0; j < 4; j++) {
            int col = bn + wn * 32 + j * 8 + (lane & 3) * 2;
            float b0 = bias[col], b1 = bias[col + 1];
            float2 v0 = make_float2(c[i][j][0] + b0, c[i][j][1] + b1);
            float2 v1 = make_float2(c[i][j][2] + b0, c[i][j][3] + b1);
            if (OUT_MODE == 0) {
                *(float2*)(C + (size_t)r * EE + col)       = v0;
                *(float2*)(C + (size_t)(r + 8) * EE + col) = v1;
            } else {
                int h_ = col >> 6, d0 = col & 63;
                int b_ = r >> 12, n_ = r & 4095;
                size_t base = ((size_t)(b_ * HH + h_) * NSEQ);
                *(float2*)(C + (base + n_)     * DD + d0) = v0;
                *(float2*)(C + (base + n_ + 8) * DD + d0) = v1;
            }
        }
    }
}

// ---------------- fused: unstabilized k-features + context/ksum/sv partials + global dd max ----------------
__global__ __launch_bounds__(256, 2) void ctx_fused(
    const float* __restrict__ K, const float* __restrict__ V,
    const float* __restrict__ proj)
{
    extern __shared__ float sm[];
    float* sPT = sm;               // [64][256]   64 KB
    float* sKF = sPT + DD * MM;    // [32][256]   32 KB
    float* sXk = sKF + 32 * MM;    // [32][64]     8 KB
    float* sV  = sXk + 32 * DD;    // [32][64]     8 KB
    __shared__ float swm[8];

    const int tid = threadIdx.x;
    const int bh  = blockIdx.x;
    const int seg = blockIdx.y;
    const int lane = tid & 31;
    const int w    = tid >> 5;
    const int m0   = lane * 8;
    const int tx   = tid & 15;     // d group (4 d)
    const int ty   = tid >> 4;     // m group (16 m)

    {
        const float4* pr = (const float4*)(proj + tid * DD);
#pragma unroll
        for (int t = 0; t < 16; t++) {
            float4 v = pr[t];
            int d = t * 4;
            sPT[(d + 0) * MM + tid] = v.x;
            sPT[(d + 1) * MM + tid] = v.y;
            sPT[(d + 2) * MM + tid] = v.z;
            sPT[(d + 3) * MM + tid] = v.w;
        }
    }

    unsigned long long cacc[16][2];
#pragma unroll
    for (int i = 0; i < 16; i++) { cacc[i][0] = 0ull; cacc[i][1] = 0ull; }
    float kacc = 0.f;
    float svacc = 0.f;
    float ddmax = -1e30f;

    for (int it = 0; it < 16; it++) {
        const int n0 = seg * 512 + it * 32;
        __syncthreads();
        {
            const float4* kr = (const float4*)(K + ((size_t)bh * NSEQ + n0) * DD);
            const float4* vr = (const float4*)(V + ((size_t)bh * NSEQ + n0) * DD);
            float4* sk4 = (float4*)sXk;
            float4* sv4 = (float4*)sV;
#pragma unroll
            for (int i = 0; i < 2; i++) {
                int f = tid * 2 + i;
                float4 kv = kr[f];
                sk4[f] = make_float4(kv.x * SCQ, kv.y * SCQ, kv.z * SCQ, kv.w * SCQ);
                sv4[f] = vr[f];
            }
        }
        __syncthreads();

        // dd + unstabilized exp -> sKF (4 rows per warp)
        {
            unsigned long long a2[4][4];
#pragma unroll
            for (int r = 0; r < 4; r++)
#pragma unroll
                for (int j = 0; j < 4; j++) a2[r][j] = 0ull;

#pragma unroll 2
            for (int d0 = 0; d0 < DD; d0 += 4) {
                float4 xv[4];
#pragma unroll
                for (int r = 0; r < 4; r++)
                    xv[r] = *(const float4*)&sXk[(w * 4 + r) * DD + d0];
#pragma unroll
                for (int dd = 0; dd < 4; dd++) {
                    const ulonglong2* bp = (const ulonglong2*)&sPT[(d0 + dd) * MM + m0];
                    ulonglong2 b01 = bp[0], b23 = bp[1];
#pragma unroll
                    for (int r = 0; r < 4; r++) {
                        unsigned long long av = pack2(f4c(xv[r], dd));
                        fma2(a2[r][0], av, b01.x); fma2(a2[r][1], av, b01.y);
                        fma2(a2[r][2], av, b23.x); fma2(a2[r][3], av, b23.y);
                    }
                }
            }
#pragma unroll
            for (int r = 0; r < 4; r++) {
                const float* xr = &sXk[(w * 4 + r) * DD];
                float x0 = xr[lane * 2], x1 = xr[lane * 2 + 1];
                float p = x0 * x0 + x1 * x1;
#pragma unroll
                for (int o = 16; o > 0; o >>= 1) p += __shfl_xor_sync(0xffffffffu, p, o);
                float sub = 0.5f * p;
                float o8[8];
#pragma unroll
                for (int j = 0; j < 4; j++) {
                    float2 f = unpack2(a2[r][j]);
                    ddmax = fmaxf(ddmax, fmaxf(f.x, f.y));
                    o8[j * 2]     = __expf(f.x - sub);
                    o8[j * 2 + 1] = __expf(f.y - sub);
                }
                float4* dst = (float4*)&sKF[(w * 4 + r) * MM + m0];
                dst[0] = *(float4*)(o8);
                dst[1] = *(float4*)(o8 + 4);
            }
        }
        __syncthreads();

#pragma unroll
        for (int r = 0; r < 32; r++) kacc += sKF[r * MM + tid];

        if (tid < 64) {
#pragma unroll
            for (int r = 0; r < 32; r++) svacc += sV[r * DD + tid];
        }

        const ulonglong2* sV2 = (const ulonglong2*)sV;
#pragma unroll 2
        for (int r = 0; r < 32; r++) {
            ulonglong2 bv = sV2[r * 16 + tx];
            const float4* kf4 = (const float4*)&sKF[r * MM + ty * 16];
            float4 kq[4];
            kq[0] = kf4[0]; kq[1] = kf4[1]; kq[2] = kf4[2]; kq[3] = kf4[3];
#pragma unroll
            for (int q = 0; q < 4; q++) {
#pragma unroll
                for (int j = 0; j < 4; j++) {
                    unsigned long long av = pack2(f4c(kq[q], j));
                    fma2(cacc[q * 4 + j][0], av, bv.x);
                    fma2(cacc[q * 4 + j][1], av, bv.y);
                }
            }
        }
    }

    g_ksump[((size_t)seg * BHn + bh) * MM + tid] = kacc;
    if (tid < 64) g_svp[((size_t)seg * BHn + bh) * DD + tid] = svacc;

    float* cp = g_ctxp + ((size_t)seg * BHn + bh) * MM * DD;
#pragma unroll
    for (int i = 0; i < 16; i++) {
        float2 f0 = unpack2(cacc[i][0]);
        float2 f1 = unpack2(cacc[i][1]);
        *(float4*)(cp + (ty * 16 + i) * DD + tx * 4) = make_float4(f0.x, f0.y, f1.x, f1.y);
    }

#pragma unroll
    for (int o = 16; o > 0; o >>= 1)
        ddmax = fmaxf(ddmax, __shfl_xor_sync(0xffffffffu, ddmax, o));
    if (lane == 0) swm[w] = ddmax;
    __syncthreads();
    if (tid == 0) {
        float m = swm[0];
#pragma unroll
        for (int i = 1; i < 8; i++) m = fmaxf(m, swm[i]);
        atomicMaxFloat(&g_kstab, m);
    }
}

// ---------------- assemble ctx + ksum from unstabilized partials ----------------
__global__ __launch_bounds__(256) void ctx_reduce_kernel() {
    const float escale = __expf(-g_kstab);
    int i = blockIdx.x * 256 + threadIdx.x;
    if (i < BHn * MM * DD) {
        int bh = i >> 14;
        int d  = i & 63;
        float U = 0.f, Sv = 0.f;
#pragma unroll
        for (int seg = 0; seg < NSEG; seg++) {
            U  += g_ctxp[(size_t)seg * BHn * MM * DD + i];
            Sv += g_svp[((size_t)seg * BHn + bh) * DD + d];
        }
        g_ctx[i] = RATIO * (escale * U + EPSK * Sv);
    }
    if (i < BHn * MM) {
        float T = 0.f;
#pragma unroll
        for (int seg = 0; seg < NSEG; seg++)
            T += g_ksump[(size_t)seg * BHn * MM + i];
        g_ksum[i] = RATIO * (escale * T + EPSK * (float)NSEQ);
    }
}

// ---------------- query features only: qf (bf16 hi/lo) + dinv ----------------
// grid (BHn, 16), block 256; each block 256 rows (8 tiles of 32). 3 CTAs/SM.
__global__ __launch_bounds__(256, 3) void qf_kernel(
    const float* __restrict__ Q, const float* __restrict__ proj,
    __nv_bfloat16* __restrict__ QFh, __nv_bfloat16* __restrict__ QFl,
    float* __restrict__ Dinv)
{
    extern __shared__ float sm[];
    float* sPT = sm;              // [64][256]  64 KB
    float* sX  = sPT + DD * MM;   // [32][64]    8 KB
    float* sKs = sX + 32 * DD;    // [256]       1 KB

    const int tid = threadIdx.x;
    const int bh  = blockIdx.x;
    const int nblk = blockIdx.y * 256;
    const int lane = tid & 31;
    const int w    = tid >> 5;
    const int m0   = lane * 8;

    {
        const float4* pr = (const float4*)(proj + tid * DD);
#pragma unroll
        for (int t = 0; t < 16; t++) {
            float4 v = pr[t];
            int d = t * 4;
            sPT[(d + 0) * MM + tid] = v.x;
            sPT[(d + 1) * MM + tid] = v.y;
            sPT[(d + 2) * MM + tid] = v.z;
            sPT[(d + 3) * MM + tid] = v.w;
        }
        sKs[tid] = g_ksum[bh * MM + tid];
    }

    for (int it = 0; it < 8; it++) {
        const int n0 = nblk + it * 32;
        __syncthreads();
        {
            const float4* xr = (const float4*)(Q + ((size_t)bh * NSEQ + n0) * DD);
            float4* sx4 = (float4*)sX;
#pragma unroll
            for (int i = 0; i < 2; i++) {
                int f = tid * 2 + i;
                float4 v = xr[f];
                sx4[f] = make_float4(v.x * SCQ, v.y * SCQ, v.z * SCQ, v.w * SCQ);
            }
        }
        __syncthreads();

        unsigned long long a2[4][4];
#pragma unroll
        for (int r = 0; r < 4; r++)
#pragma unroll
            for (int j = 0; j < 4; j++) a2[r][j] = 0ull;

#pragma unroll 2
        for (int d0 = 0; d0 < DD; d0 += 4) {
            float4 xv[4];
#pragma unroll
            for (int r = 0; r < 4; r++)
                xv[r] = *(const float4*)&sX[(w * 4 + r) * DD + d0];
#pragma unroll
            for (int dd = 0; dd < 4; dd++) {
                const ulonglong2* bp = (const ulonglong2*)&sPT[(d0 + dd) * MM + m0];
                ulonglong2 b01 = bp[0], b23 = bp[1];
#pragma unroll
                for (int r = 0; r < 4; r++) {
                    unsigned long long av = pack2(f4c(xv[r], dd));
                    fma2(a2[r][0], av, b01.x); fma2(a2[r][1], av, b01.y);
                    fma2(a2[r][2], av, b23.x); fma2(a2[r][3], av, b23.y);
                }
            }
        }

#pragma unroll
        for (int r = 0; r < 4; r++) {
            float v8[8];
#pragma unroll
            for (int j = 0; j < 4; j++) {
                float2 f = unpack2(a2[r][j]);
                v8[j * 2] = f.x; v8[j * 2 + 1] = f.y;
            }
            float mx = v8[0];
#pragma unroll
            for (int j = 1; j < 8; j++) mx = fmaxf(mx, v8[j]);
#pragma unroll
            for (int o = 16; o > 0; o >>= 1)
                mx = fmaxf(mx, __shfl_xor_sync(0xffffffffu, mx, o));

            const float* xr = &sX[(w * 4 + r) * DD];
            float x0 = xr[lane * 2], x1 = xr[lane * 2 + 1];
            float p = x0 * x0 + x1 * x1;
#pragma unroll
            for (int o = 16; o > 0; o >>= 1) p += __shfl_xor_sync(0xffffffffu, p, o);
            float sub = 0.5f * p + mx;

            float o8[8];
            float dp = 0.f;
            ushort hb[8], lb[8];
#pragma unroll
            for (int j = 0; j < 8; j++) {
                o8[j] = RATIO * (__expf(v8[j] - sub) + EPSK);
                dp += o8[j] * sKs[m0 + j];
                __nv_bfloat16 h = __float2bfloat16(o8[j]);
                hb[j] = __bfloat16_as_ushort(h);
                lb[j] = __bfloat16_as_ushort(__float2bfloat16(o8[j] - __bfloat162float(h)));
            }
#pragma unroll
            for (int o = 16; o > 0; o >>= 1) dp += __shfl_xor_sync(0xffffffffu, dp, o);

            const int n = n0 + w * 4 + r;
            size_t base = ((size_t)bh * NSEQ + n) * MM + m0;
            uint4 hv, lv;
            hv.x = ((uint32_t)hb[1] << 16) | hb[0]; hv.y = ((uint32_t)hb[3] << 16) | hb[2];
            hv.z = ((uint32_t)hb[5] << 16) | hb[4]; hv.w = ((uint32_t)hb[7] << 16) | hb[6];
            lv.x = ((uint32_t)lb[1] << 16) | lb[0]; lv.y = ((uint32_t)lb[3] << 16) | lb[2];
            lv.z = ((uint32_t)lb[5] << 16) | lb[4]; lv.w = ((uint32_t)lb[7] << 16) | lb[6];
            *(uint4*)(QFh + base) = hv;
            *(uint4*)(QFl + base) = lv;
            if (lane == 0) Dinv[(size_t)bh * NSEQ + n] = 1.f / dp;
        }
    }
}

// ---------------- yv_gemm: per-head y = qf @ ctx^T, * dinv, bf16-split output ----------------
// grid (32 n-tiles, 64 bh), block 256. Tile 128(n) x 64(d), K=256, 3 split passes.
// B (ctx^T) resident in smem (hi/lo), A (qf) streamed 3-stage.
#define YV_NCHUNK 12       // 3 passes * 256/64
#define YV_ASTG  16384     // A stage: 128 rows x 128B

__global__ __launch_bounds__(256, 2) void yv_gemm(
    const __nv_bfloat16* __restrict__ QFh, const __nv_bfloat16* __restrict__ QFl,
    __nv_bfloat16* __restrict__ OutH, __nv_bfloat16* __restrict__ OutL)
{
    extern __shared__ __align__(128) char gsm[];
    // layout: A stages 3x16KB @0, Bh @49152 (32KB), Bl @81920 (32KB)
    const uint32_t smem_base = smem_u32(gsm);
    const uint32_t sBH = smem_base + 49152;
    const uint32_t sBL = smem_base + 81920;

    const int tid  = threadIdx.x;
    const int lane = tid & 31;
    const int wid  = tid >> 5;
    const int wm   = wid & 1;      // 2 warps along M(n)
    const int wn   = wid >> 1;     // 4 warps along N(d): 16 each
    const int bh   = blockIdx.y;
    const int bm   = blockIdx.x * 128;
    const int b_   = bh >> 4;
    const int h_   = bh & 15;

    // Convert resident B: ctx[bh][m][d] fp32 -> smem K-major [d-row][m] bf16 hi/lo, swizzled
    {
        const float* cbase = g_ctx + (size_t)bh * MM * DD;
#pragma unroll
        for (int t = 0; t < 64; t++) {
            int e = t * 256 + tid;       // 0..16383
            int m = e >> 6, d = e & 63;
            float val = cbase[e];
            __nv_bfloat16 h = __float2bfloat16(val);
            __nv_bfloat16 l = __float2bfloat16(val - __bfloat162float(h));
            int mc = m & 63;
            uint32_t off = (uint32_t)((m >> 6) * 8192 + d * 128 + (((mc >> 3) ^ (d & 7)) << 4) + (mc & 7) * 2);
            *(ushort*)((char*)gsm + 49152 + off) = __bfloat16_as_ushort(h);
            *(ushort*)((char*)gsm + 81920 + off) = __bfloat16_as_ushort(l);
        }
    }

    const __nv_bfloat16* pA[3] = {QFh, QFh, QFl};

    float c[4][2][4];
#pragma unroll
    for (int i = 0; i < 4; i++)
#pragma unroll
        for (int j = 0; j < 2; j++)
#pragma unroll
            for (int q = 0; q < 4; q++) c[i][j][q] = 0.f;

    auto prefetchA = [&](int s, int stage) {
        if (s < YV_NCHUNK) {
            const int ph = s >> 2;
            const int kk = (s & 3) << 6;
            const __nv_bfloat16* gA = pA[ph] + (size_t)bh * NSEQ * MM;
            const uint32_t aB = smem_base + stage * YV_ASTG;
#pragma unroll
            for (int it = 0; it < 4; it++) {
                int idx = it * 256 + tid;
                int row = idx >> 3;
                int pb  = idx & 7;
                uint32_t doff = row * 128 + ((pb ^ (row & 7)) << 4);
                const void* srcA = gA + (size_t)(bm + row) * MM + kk + pb * 8;
                asm volatile("cp.async.cg.shared.global [%0], [%1], 16;" :: "r"(aB + doff), "l"(srcA));
            }
        }
        asm volatile("cp.async.commit_group;" ::: "memory");
    };

    prefetchA(0, 0);
    prefetchA(1, 1);
    __syncthreads();   // B conversion complete before mainloop reads it

    for (int s = 0; s < YV_NCHUNK; s++) {
        const int stage = s % 3;
        asm volatile("cp.async.wait_group 1;" ::: "memory");
        __syncthreads();
        prefetchA(s + 2, (s + 2) % 3);

        const uint32_t cA = smem_base + stage * YV_ASTG;
        const int ph = s >> 2;
        const uint32_t cBbase = (ph == 1) ? sBL : sBH;   // pass 0: Ah*Bh, 1: Ah*Bl, 2: Al*Bh
        const uint32_t cB = cBbase + (uint32_t)((s & 3) * 8192);

#pragma unroll
        for (int ks = 0; ks < 4; ks++) {
            uint32_t bf[2][2];
            {
                int row = wn * 16 + ((lane >> 4) << 3) + (lane & 7);
                int pb  = ks * 2 + ((lane >> 3) & 1);
                uint32_t ad = cB + row * 128 + ((pb ^ (row & 7)) << 4);
                uint32_t t4[4];
                ldmx4(t4, ad);
                bf[0][0] = t4[0]; bf[0][1] = t4[1];
                bf[1][0] = t4[2]; bf[1][1] = t4[3];
            }
#pragma unroll
            for (int i = 0; i < 4; i++) {
                int r0 = wm * 64 + i * 16;
                int row = r0 + (((lane >> 3) & 1) << 3) + (lane & 7);
                int pb  = ks * 2 + ((lane >> 4) & 1);
                uint32_t ad = cA + row * 128 + ((pb ^ (row & 7)) << 4);
                uint32_t af[4];
                ldmx4(af, ad);
#pragma unroll
                for (int j = 0; j < 2; j++)
                    mma16816(c[i][j], af, bf[j]);
            }
        }
        __syncthreads();
    }

    // epilogue: scale by dinv, split bf16 hi/lo, write to GEMM input layout [b,n][h*64+d]
#pragma unroll
    for (int i = 0; i < 4; i++) {
        int rl = wm * 64 + i * 16 + (lane >> 2);
        int nA = bm + rl;
        int nB = nA + 8;
        float dA = g_dinv[(size_t)bh * NSEQ + nA];
        float dB = g_dinv[(size_t)bh * NSEQ + nB];
#pragma unroll
        for (int j = 0; j < 2; j++) {
            int col = wn * 16 + j * 8 + (lane & 3) * 2;
            float vA0 = c[i][j][0] * dA, vA1 = c[i][j][1] * dA;
            float vB0 = c[i][j][2] * dB, vB1 = c[i][j][3] * dB;
            __nv_bfloat16 hA0 = __float2bfloat16(vA0), hA1 = __float2bfloat16(vA1);
            __nv_bfloat16 hB0 = __float2bfloat16(vB0), hB1 = __float2bfloat16(vB1);
            uint32_t hvA = ((uint32_t)__bfloat16_as_ushort(hA1) << 16) | __bfloat16_as_ushort(hA0);
            uint32_t lvA = ((uint32_t)__bfloat16_as_ushort(__float2bfloat16(vA1 - __bfloat162float(hA1))) << 16)
                         | __bfloat16_as_ushort(__float2bfloat16(vA0 - __bfloat162float(hA0)));
            uint32_t hvB = ((uint32_t)__bfloat16_as_ushort(hB1) << 16) | __bfloat16_as_ushort(hB0);
            uint32_t lvB = ((uint32_t)__bfloat16_as_ushort(__float2bfloat16(vB1 - __bfloat162float(hB1))) << 16)
                         | __bfloat16_as_ushort(__float2bfloat16(vB0 - __bfloat162float(hB0)));
            size_t idxA = ((size_t)(b_ * NSEQ + nA)) * EE + h_ * DD + col;
            size_t idxB = ((size_t)(b_ * NSEQ + nB)) * EE + h_ * DD + col;
            *(uint32_t*)(OutH + idxA) = hvA;
            *(uint32_t*)(OutL + idxA) = lvA;
            *(uint32_t*)(OutH + idxB) = hvB;
            *(uint32_t*)(OutL + idxB) = lvB;
        }
    }
}

// ---------------- launch ----------------
extern "C" void kernel_launch(void* const* d_in, const int* in_sizes, int n_in,
                              void* d_out, int out_size) {
    const float* x    = (const float*)d_in[0];
    const float* Wq   = (const float*)d_in[1];
    const float* bq   = (const float*)d_in[2];
    const float* Wk   = (const float*)d_in[3];
    const float* bk   = (const float*)d_in[4];
    const float* Wv   = (const float*)d_in[5];
    const float* bv   = (const float*)d_in[6];
    const float* Wo   = (const float*)d_in[7];
    const float* bo   = (const float*)d_in[8];
    const float* proj = (const float*)d_in[9];
    float* out = (float*)d_out;

    float *pq, *pk, *pv, *pdinv;
    __nv_bfloat16 *pah, *pal, *pwh, *pwl, *pqfh, *pqfl;
    cudaGetSymbolAddress((void**)&pq,   g_q);
    cudaGetSymbolAddress((void**)&pk,   g_k);
    cudaGetSymbolAddress((void**)&pv,   g_v);
    cudaGetSymbolAddress((void**)&pdinv, g_dinv);
    cudaGetSymbolAddress((void**)&pah,  g_ah);
    cudaGetSymbolAddress((void**)&pal,  g_al);
    cudaGetSymbolAddress((void**)&pwh,  g_wh);
    cudaGetSymbolAddress((void**)&pwl,  g_wl);
    cudaGetSymbolAddress((void**)&pqfh, g_qfh);
    cudaGetSymbolAddress((void**)&pqfl, g_qfl);

    const int GEMM_SMEM = 3 * STG_BYTES;                                                 // 98304
    const int CTXF_SMEM = (DD * MM + 32 * MM + 32 * DD + 32 * DD) * (int)sizeof(float);  // 114688
    const int QF_SMEM   = (DD * MM + 32 * DD + MM) * (int)sizeof(float);                 // 74752
    const int YV_SMEM   = 3 * YV_ASTG + 2 * 32768;                                       // 114688
    cudaFuncSetAttribute(gemm_mma<0>, cudaFuncAttributeMaxDynamicSharedMemorySize, GEMM_SMEM);
    cudaFuncSetAttribute(gemm_mma<1>, cudaFuncAttributeMaxDynamicSharedMemorySize, GEMM_SMEM);
    cudaFuncSetAttribute(ctx_fused,  cudaFuncAttributeMaxDynamicSharedMemorySize, CTXF_SMEM);
    cudaFuncSetAttribute(qf_kernel,  cudaFuncAttributeMaxDynamicSharedMemorySize, QF_SMEM);
    cudaFuncSetAttribute(yv_gemm,    cudaFuncAttributeMaxDynamicSharedMemorySize, YV_SMEM);

    init_kernel<<<1, 32>>>();

    split_kernel<<<2048, 256>>>(x, pah, pal, TT * EE / 4);

    dim3 gg(EE / 128, TT / 128);

    split_kernel<<<512, 256>>>(Wq, pwh, pwl, EE * EE / 4);
    gemm_mma<1><<<gg, 256, GEMM_SMEM>>>(pah, pal, pwh, pwl, bq, pq);
    split_kernel<<<512, 256>>>(Wk, pwh, pwl, EE * EE / 4);
    gemm_mma<1><<<gg, 256, GEMM_SMEM>>>(pah, pal, pwh, pwl, bk, pk);
    split_kernel<<<512, 256>>>(Wv, pwh, pwl, EE * EE / 4);
    gemm_mma<1><<<gg, 256, GEMM_SMEM>>>(pah, pal, pwh, pwl, bv, pv);

    ctx_fused<<<dim3(BHn, NSEG), 256, CTXF_SMEM>>>(pk, pv, proj);
    ctx_reduce_kernel<<<(BHn * MM * DD + 255) / 256, 256>>>();

    qf_kernel<<<dim3(BHn, 16), 256, QF_SMEM>>>(pq, proj, pqfh, pqfl, pdinv);

    yv_gemm<<<dim3(NSEQ / 128, BHn), 256, YV_SMEM>>>(pqfh, pqfl, pah, pal);

    split_kernel<<<512, 256>>>(Wo, pwh, pwl, EE * EE / 4);
    gemm_mma<0><<<gg, 256, GEMM_SMEM>>>(pah, pal, pwh, pwl, bo, out);
}